// round 9
// baseline (speedup 1.0000x reference)
#include <cuda_runtime.h>
#include <cstdint>
#include <cstddef>

using u64 = unsigned long long;

// Problem constants
constexpr int B_ = 64;
constexpr int L_ = 512;
constexpr int E_ = 512;
constexpr int G_ = 1536;          // 3*H
constexpr int M_ = B_ * L_;       // 32768 rows per direction
constexpr float LN_EPS = 1e-5f;

// Scratch (device globals: allocation-free)
__device__ float g_px[2ull * 32768ull * 1536ull];   // LN3(x @ Wx) per dir
__device__ float g_ph[2 * 64 * 1536];               // per-step h @ Wh
__device__ float g_hT[2 * 512 * 64];                // hidden transposed [dir][k][b]
__device__ unsigned g_cnt2[2];                      // per-dir grid barrier
__device__ unsigned g_gen2[2];

// ---------------- packed f32x2 helpers ----------------
__device__ __forceinline__ u64 pack2(float x, float y) {
    u64 r; asm("mov.b64 %0,{%1,%2};" : "=l"(r) : "f"(x), "f"(y)); return r;
}
__device__ __forceinline__ void unpack2(float& x, float& y, u64 v) {
    asm("mov.b64 {%0,%1},%2;" : "=f"(x), "=f"(y) : "l"(v));
}
__device__ __forceinline__ void fma2(u64& d, u64 a, u64 b) {
    asm("fma.rn.f32x2 %0,%1,%2,%0;" : "+l"(d) : "l"(a), "l"(b));
}
__device__ __forceinline__ u64 add2(u64 a, u64 b) {
    u64 d; asm("add.rn.f32x2 %0,%1,%2;" : "=l"(d) : "l"(a), "l"(b)); return d;
}

// ---------------------------------------------------------------------------
// Kernel 1: px = xs @ Wx.  BM=128, BN=128, BK=16, 256 threads.
// 8m x 8n thread tile; n organized as f32x2 pairs, A broadcast + dup.
// ---------------------------------------------------------------------------
__global__ __launch_bounds__(256) void gemm_px_kernel(
    const float* __restrict__ xs,
    const float* __restrict__ Wxf,
    const float* __restrict__ Wxb)
{
    constexpr int BK = 16, LDA = 132;
    __shared__ float As[BK * LDA];     // A transposed [k][m]
    __shared__ float Bs[BK * 128];     // B [k][n]

    const int dir = blockIdx.z;
    const float* W = dir ? Wxb : Wxf;
    const int m0 = blockIdx.y * 128;
    const int n0 = blockIdx.x * 128;
    const int t  = threadIdx.x;
    const int tx = t & 15;
    const int ty = t >> 4;

    u64 acc[8][4];
#pragma unroll
    for (int m = 0; m < 8; m++)
#pragma unroll
        for (int np = 0; np < 4; np++) acc[m][np] = 0ull;

    for (int kt = 0; kt < E_; kt += BK) {
#pragma unroll
        for (int i = 0; i < 2; i++) {
            int idx = t + 256 * i;
            int row = idx >> 2;
            int c4  = idx & 3;
            int m   = m0 + row;
            int b   = m >> 9;
            int s   = m & 511;
            int torig = dir ? (511 - s) : s;
            const float4 va = *reinterpret_cast<const float4*>(
                xs + ((size_t)(b * 512 + torig)) * 512 + kt + c4 * 4);
            As[(c4 * 4 + 0) * LDA + row] = va.x;
            As[(c4 * 4 + 1) * LDA + row] = va.y;
            As[(c4 * 4 + 2) * LDA + row] = va.z;
            As[(c4 * 4 + 3) * LDA + row] = va.w;
        }
#pragma unroll
        for (int i = 0; i < 2; i++) {
            int idx = t + 256 * i;
            int row = idx >> 5;
            int c4  = idx & 31;
            const float4 vb = *reinterpret_cast<const float4*>(
                W + (size_t)(kt + row) * G_ + n0 + c4 * 4);
            *reinterpret_cast<float4*>(Bs + row * 128 + c4 * 4) = vb;
        }
        __syncthreads();

#pragma unroll
        for (int k = 0; k < BK; k++) {
            float4 a0 = *reinterpret_cast<const float4*>(As + k * LDA + ty * 8);
            float4 a1 = *reinterpret_cast<const float4*>(As + k * LDA + ty * 8 + 4);
            u64 ad[8];
            ad[0] = pack2(a0.x, a0.x); ad[1] = pack2(a0.y, a0.y);
            ad[2] = pack2(a0.z, a0.z); ad[3] = pack2(a0.w, a0.w);
            ad[4] = pack2(a1.x, a1.x); ad[5] = pack2(a1.y, a1.y);
            ad[6] = pack2(a1.z, a1.z); ad[7] = pack2(a1.w, a1.w);
            const ulonglong2 q0 = *reinterpret_cast<const ulonglong2*>(Bs + k * 128 + tx * 4);
            const ulonglong2 q1 = *reinterpret_cast<const ulonglong2*>(Bs + k * 128 + 64 + tx * 4);
            u64 bp[4] = {q0.x, q0.y, q1.x, q1.y};
#pragma unroll
            for (int m = 0; m < 8; m++) {
                fma2(acc[m][0], ad[m], bp[0]);
                fma2(acc[m][1], ad[m], bp[1]);
                fma2(acc[m][2], ad[m], bp[2]);
                fma2(acc[m][3], ad[m], bp[3]);
            }
        }
        __syncthreads();
    }

    float* C = g_px + (size_t)dir * M_ * G_;
#pragma unroll
    for (int m = 0; m < 8; m++) {
        float* r = C + (size_t)(m0 + ty * 8 + m) * G_ + n0;
        ulonglong2 s0; s0.x = acc[m][0]; s0.y = acc[m][1];
        ulonglong2 s1; s1.x = acc[m][2]; s1.y = acc[m][3];
        *reinterpret_cast<ulonglong2*>(r + tx * 4)      = s0;
        *reinterpret_cast<ulonglong2*>(r + 64 + tx * 4) = s1;
    }
}

// ---------------------------------------------------------------------------
// Kernel 2: in-place LN3 over g_px.
// ---------------------------------------------------------------------------
__global__ __launch_bounds__(128) void ln3_kernel(
    const float* __restrict__ gf, const float* __restrict__ bf,
    const float* __restrict__ gb, const float* __restrict__ bb)
{
    const int blk   = blockIdx.x;
    const int chunk = blk % 3;
    const int row   = blk / 3;
    const int dir   = row >> 15;
    const float* g  = (dir ? gb : gf) + chunk * 512;
    const float* be = (dir ? bb : bf) + chunk * 512;
    float* p = g_px + (size_t)row * G_ + chunk * 512;

    const int t = threadIdx.x;
    float4 v = reinterpret_cast<float4*>(p)[t];
    float s = v.x + v.y + v.z + v.w;
    float q = v.x * v.x + v.y * v.y + v.z * v.z + v.w * v.w;
#pragma unroll
    for (int o = 16; o > 0; o >>= 1) {
        s += __shfl_down_sync(0xffffffffu, s, o);
        q += __shfl_down_sync(0xffffffffu, q, o);
    }
    __shared__ float ss[4], sq[4];
    __shared__ float st[2];
    const int w = t >> 5, lane = t & 31;
    if (lane == 0) { ss[w] = s; sq[w] = q; }
    __syncthreads();
    if (t == 0) {
        float S = ss[0] + ss[1] + ss[2] + ss[3];
        float Q = sq[0] + sq[1] + sq[2] + sq[3];
        float mu = S * (1.f / 512.f);
        float var = Q * (1.f / 512.f) - mu * mu;
        st[0] = mu;
        st[1] = rsqrtf(var + LN_EPS);
    }
    __syncthreads();
    const float mu = st[0], rs = st[1];
    float4 gv = reinterpret_cast<const float4*>(g)[t];
    float4 bv = reinterpret_cast<const float4*>(be)[t];
    v.x = (v.x - mu) * rs * gv.x + bv.x;
    v.y = (v.y - mu) * rs * gv.y + bv.y;
    v.z = (v.z - mu) * rs * gv.z + bv.z;
    v.w = (v.w - mu) * rs * gv.w + bv.w;
    reinterpret_cast<float4*>(p)[t] = v;
}

// ---------------------------------------------------------------------------
// Kernel 3: persistent recurrence, 128 blocks, 256 threads.
// G phase: 6j x 8b thread tile, b-pair FFMA2, Wh pre-duplicated in SMEM.
// ---------------------------------------------------------------------------
constexpr int SLICE = 24;

__device__ __forceinline__ void gridbar(int dir)
{
    __syncthreads();
    if (threadIdx.x == 0) {
        unsigned gen = *(volatile unsigned*)&g_gen2[dir];
        __threadfence();
        if (atomicAdd(&g_cnt2[dir], 1u) == 63u) {
            g_cnt2[dir] = 0u;
            __threadfence();
            *(volatile unsigned*)&g_gen2[dir] = gen + 1u;
        } else {
            while (*(volatile unsigned*)&g_gen2[dir] == gen) { __nanosleep(16); }
            __threadfence();
        }
    }
    __syncthreads();
}

__device__ __forceinline__ void stage_chunk(const float* gsrc, const float* dst, int t)
{
    unsigned saddr = (unsigned)__cvta_generic_to_shared(dst);
#pragma unroll
    for (int i = 0; i < 8; i++) {
        int off = (t + 256 * i) * 16;
        asm volatile("cp.async.cg.shared.global [%0], [%1], 16;"
                     :: "r"(saddr + off), "l"((const char*)gsrc + off) : "memory");
    }
    asm volatile("cp.async.commit_group;" ::: "memory");
}

__global__ __launch_bounds__(256) void rnn_kernel(
    const float* __restrict__ Whf, const float* __restrict__ Whb,
    const float* __restrict__ ghf, const float* __restrict__ bhf,
    const float* __restrict__ ghb, const float* __restrict__ bhb,
    const float* __restrict__ mask, float* __restrict__ out)
{
    extern __shared__ float smem[];
    u64* sWhd = reinterpret_cast<u64*>(smem);   // [512][32] u64 (24 used/row) = 128KB
    float* sh  = smem + 32768;                  // 2 x (128k x 64b) staging = 64KB
    __shared__ float sred[48];
    __shared__ float sstat[6];

    const int t   = threadIdx.x;
    const int blk = blockIdx.x;
    const int dir = blk >> 6;
    const int sub = blk & 63;             // G: j-slice id. U: batch row.
    const float* Wh = dir ? Whb : Whf;
    const float* gh = dir ? ghb : ghf;
    const float* bh = dir ? bhb : bhf;
    const int j0 = sub * SLICE;

    // G-phase decode: q = k-split warp (8), jg = j-group (4), bg = b-group (8)
    const int q    = t >> 5;
    const int lane = t & 31;
    const int jg   = (t >> 3) & 3;
    const int bg   = t & 7;

    // One-time: Wh slice -> SMEM, each value duplicated as (w,w) u64 pairs,
    // layout [k][jg][8] u64 (6 used per jg).
    for (int i = t; i < 512 * SLICE; i += 256) {
        int k  = i / SLICE;
        int jj = i - k * SLICE;
        float w = Wh[(size_t)k * G_ + j0 + jj];
        sWhd[k * 32 + (jj / 6) * 8 + (jj % 6)] = pack2(w, w);
    }
    // One-time: zero this block's hT column range
    for (int i = t; i < 512; i += 256)
        g_hT[dir * 32768 + sub * 512 + i] = 0.f;

    // U-phase constants
    float gg6[6], bb6[6];
#pragma unroll
    for (int i = 0; i < 6; i++) {
        int j = (i >> 1) * 512 + (i & 1) * 256 + t;
        gg6[i] = gh[j];
        bb6[i] = bh[j];
    }
    const float* pxrow = g_px + ((size_t)(dir * 64 + sub)) * ((size_t)L_ * G_);
    const float* hTg = g_hT + dir * 32768;
    float* phd = g_ph + dir * 64 * G_;
    const float* mrow = mask + sub * 512;

    float h0 = 0.f, h1 = 0.f;             // hidden state in registers

    gridbar(dir);                          // hT zeros visible

    for (int s = 0; s < L_; s++) {
        // ---- prefetch U-phase inputs ----
        const int torig = dir ? (511 - s) : s;
        const float* pxt = pxrow + (size_t)s * G_;
        const float m   = __ldg(mrow + torig);
        const float xz0 = __ldg(pxt + t);
        const float xr0 = __ldg(pxt + 512 + t);
        const float xg0 = __ldg(pxt + 1024 + t);
        const float xz1 = __ldg(pxt + 256 + t);
        const float xr1 = __ldg(pxt + 768 + t);
        const float xg1 = __ldg(pxt + 1280 + t);

        // ---- Phase G: ph[b][j0..j0+23] = sum_k hT[k][b] * Wh[k][j] ----
        u64 acc[24];                       // [j][bp]: j 0..5, bp 0..3 (b-pairs)
#pragma unroll
        for (int i = 0; i < 24; i++) acc[i] = 0ull;

        stage_chunk(hTg,        sh,        t);   // chunk 0 -> buf0
        stage_chunk(hTg + 8192, sh + 8192, t);   // chunk 1 -> buf1

        for (int c = 0; c < 4; c++) {
            if (c == 3) asm volatile("cp.async.wait_group 0;" ::: "memory");
            else        asm volatile("cp.async.wait_group 1;" ::: "memory");
            __syncthreads();

            const u64*   wb = sWhd + (c * 128 + q * 16) * 32 + jg * 8;
            const float* hb = sh + (c & 1) * 8192 + (q * 16) * 64 + bg * 8;
#pragma unroll
            for (int kk = 0; kk < 16; kk++) {
                const ulonglong2* w2 = reinterpret_cast<const ulonglong2*>(wb + kk * 32);
                ulonglong2 w01 = w2[0], w23 = w2[1], w45 = w2[2];
                const ulonglong2* h2 = reinterpret_cast<const ulonglong2*>(hb + kk * 64);
                ulonglong2 hA = h2[0], hB = h2[1];
                fma2(acc[0],  w01.x, hA.x); fma2(acc[1],  w01.x, hA.y);
                fma2(acc[2],  w01.x, hB.x); fma2(acc[3],  w01.x, hB.y);
                fma2(acc[4],  w01.y, hA.x); fma2(acc[5],  w01.y, hA.y);
                fma2(acc[6],  w01.y, hB.x); fma2(acc[7],  w01.y, hB.y);
                fma2(acc[8],  w23.x, hA.x); fma2(acc[9],  w23.x, hA.y);
                fma2(acc[10], w23.x, hB.x); fma2(acc[11], w23.x, hB.y);
                fma2(acc[12], w23.y, hA.x); fma2(acc[13], w23.y, hA.y);
                fma2(acc[14], w23.y, hB.x); fma2(acc[15], w23.y, hB.y);
                fma2(acc[16], w45.x, hA.x); fma2(acc[17], w45.x, hA.y);
                fma2(acc[18], w45.x, hB.x); fma2(acc[19], w45.x, hB.y);
                fma2(acc[20], w45.y, hA.x); fma2(acc[21], w45.y, hA.y);
                fma2(acc[22], w45.y, hB.x); fma2(acc[23], w45.y, hB.y);
            }
            __syncthreads();
            if (c < 2)
                stage_chunk(hTg + (c + 2) * 8192, sh + (c & 1) * 8192, t);
        }

        // ---- 8-way k-split tree reduction through staging buffer ----
        {
            u64* red = reinterpret_cast<u64*>(sh);
            if (q >= 4) {
                u64* r = red + ((q - 4) * 32 + lane) * 24;
#pragma unroll
                for (int i = 0; i < 24; i++) r[i] = acc[i];
            }
            __syncthreads();
            if (q < 4) {
                const u64* r = red + (q * 32 + lane) * 24;
#pragma unroll
                for (int i = 0; i < 24; i++) acc[i] = add2(acc[i], r[i]);
            }
            __syncthreads();
            if (q == 2 || q == 3) {
                u64* r = red + ((q - 2) * 32 + lane) * 24;
#pragma unroll
                for (int i = 0; i < 24; i++) r[i] = acc[i];
            }
            __syncthreads();
            if (q < 2) {
                const u64* r = red + (q * 32 + lane) * 24;
#pragma unroll
                for (int i = 0; i < 24; i++) acc[i] = add2(acc[i], r[i]);
            }
            __syncthreads();
            if (q == 1) {
                u64* r = red + lane * 24;
#pragma unroll
                for (int i = 0; i < 24; i++) r[i] = acc[i];
            }
            __syncthreads();
            if (q == 0) {
                const u64* r = red + lane * 24;
#pragma unroll
                for (int i = 0; i < 24; i++) acc[i] = add2(acc[i], r[i]);
                // write ph[b][j] (scalar; 48 stores on one warp)
                const int jb = j0 + jg * 6;
#pragma unroll
                for (int j = 0; j < 6; j++)
#pragma unroll
                    for (int bp = 0; bp < 4; bp++) {
                        float f0, f1;
                        unpack2(f0, f1, acc[j * 4 + bp]);
                        int b0 = bg * 8 + bp * 2;
                        phd[(size_t)b0 * G_ + jb + j]       = f0;
                        phd[(size_t)(b0 + 1) * G_ + jb + j] = f1;
                    }
            }
        }
        gridbar(dir);

        // ---- Phase U: LN3(ph) + GRU gates for batch row `sub` ----
        const float* phr = phd + (size_t)sub * G_;
        float v0 = __ldcg(phr + t);
        float v1 = __ldcg(phr + 256 + t);
        float v2 = __ldcg(phr + 512 + t);
        float v3 = __ldcg(phr + 768 + t);
        float v4 = __ldcg(phr + 1024 + t);
        float v5 = __ldcg(phr + 1280 + t);

        float p0 = v0 + v1, p1 = v2 + v3, p2 = v4 + v5;
        float q0 = v0 * v0 + v1 * v1;
        float q1 = v2 * v2 + v3 * v3;
        float q2 = v4 * v4 + v5 * v5;
#pragma unroll
        for (int o = 16; o > 0; o >>= 1) {
            p0 += __shfl_down_sync(0xffffffffu, p0, o);
            p1 += __shfl_down_sync(0xffffffffu, p1, o);
            p2 += __shfl_down_sync(0xffffffffu, p2, o);
            q0 += __shfl_down_sync(0xffffffffu, q0, o);
            q1 += __shfl_down_sync(0xffffffffu, q1, o);
            q2 += __shfl_down_sync(0xffffffffu, q2, o);
        }
        if (lane == 0) {
            sred[q * 6 + 0] = p0; sred[q * 6 + 1] = p1; sred[q * 6 + 2] = p2;
            sred[q * 6 + 3] = q0; sred[q * 6 + 4] = q1; sred[q * 6 + 5] = q2;
        }
        __syncthreads();
        if (t < 6) {
            float tot = 0.f;
#pragma unroll
            for (int w = 0; w < 8; w++) tot += sred[w * 6 + t];
            sstat[t] = tot;
        }
        __syncthreads();
        const float mu0 = sstat[0] * (1.f / 512.f);
        const float mu1 = sstat[1] * (1.f / 512.f);
        const float mu2 = sstat[2] * (1.f / 512.f);
        const float rs0 = rsqrtf(sstat[3] * (1.f / 512.f) - mu0 * mu0 + LN_EPS);
        const float rs1 = rsqrtf(sstat[4] * (1.f / 512.f) - mu1 * mu1 + LN_EPS);
        const float rs2 = rsqrtf(sstat[5] * (1.f / 512.f) - mu2 * mu2 + LN_EPS);

        float* outt = out + ((size_t)sub * 512 + torig) * 1024 + dir * 512;
        float* hwr = g_hT + dir * 32768;

        // half 0: column t
        {
            float phz  = (v0 - mu0) * rs0 * gg6[0] + bb6[0];
            float phrv = (v2 - mu1) * rs1 * gg6[2] + bb6[2];
            float phgv = (v4 - mu2) * rs2 * gg6[4] + bb6[4];
            float z  = 1.f / (1.f + __expf(-(xz0 + phz)));
            float r  = 1.f / (1.f + __expf(-(xr0 + phrv)));
            float gv = tanhf(xg0 + r * phgv);
            h0 = h0 + m * z * (gv - h0);
            hwr[t * 64 + sub] = h0;
            outt[t] = h0 * m;
        }
        // half 1: column t+256
        {
            float phz  = (v1 - mu0) * rs0 * gg6[1] + bb6[1];
            float phrv = (v3 - mu1) * rs1 * gg6[3] + bb6[3];
            float phgv = (v5 - mu2) * rs2 * gg6[5] + bb6[5];
            float z  = 1.f / (1.f + __expf(-(xz1 + phz)));
            float r  = 1.f / (1.f + __expf(-(xr1 + phrv)));
            float gv = tanhf(xg1 + r * phgv);
            h1 = h1 + m * z * (gv - h1);
            hwr[(t + 256) * 64 + sub] = h1;
            outt[t + 256] = h1 * m;
        }
        gridbar(dir);
    }
}

// ---------------------------------------------------------------------------
extern "C" void kernel_launch(void* const* d_in, const int* in_sizes, int n_in,
                              void* d_out, int out_size)
{
    const float* xs    = (const float*)d_in[0];
    const float* xmask = (const float*)d_in[1];
    const float* fWx   = (const float*)d_in[2];
    const float* fWh   = (const float*)d_in[3];
    const float* fgx   = (const float*)d_in[4];
    const float* fbx   = (const float*)d_in[5];
    const float* fgh   = (const float*)d_in[6];
    const float* fbh   = (const float*)d_in[7];
    const float* bWx   = (const float*)d_in[8];
    const float* bWh   = (const float*)d_in[9];
    const float* bgx   = (const float*)d_in[10];
    const float* bbx   = (const float*)d_in[11];
    const float* bgh   = (const float*)d_in[12];
    const float* bbh   = (const float*)d_in[13];
    float* out = (float*)d_out;

    // dynamic smem: dup Wh (512*32 u64 = 128KB) + staging (64KB) = 192KB
    const int rnn_smem = 32768 * 4 + 16384 * 4;   // 196608 B
    cudaFuncSetAttribute(rnn_kernel, cudaFuncAttributeMaxDynamicSharedMemorySize, rnn_smem);

    // 1) px = xs @ Wx (both directions; dir=1 uses time-reversed xs)
    dim3 ggrid(G_ / 128, M_ / 128, 2);
    gemm_px_kernel<<<ggrid, 256>>>(xs, fWx, bWx);

    // 2) in-place LN3 on px
    ln3_kernel<<<2 * M_ * 3, 128>>>(fgx, fbx, bgx, bbx);

    // 3) persistent bidirectional GRU recurrence
    rnn_kernel<<<128, 256, rnn_smem>>>(fWh, bWh, fgh, fbh, bgh, bbh, xmask, out);
}

// round 10
// speedup vs baseline: 1.0433x; 1.0433x over previous
#include <cuda_runtime.h>
#include <cstdint>
#include <cstddef>

using u64 = unsigned long long;

// Problem constants
constexpr int B_ = 64;
constexpr int L_ = 512;
constexpr int E_ = 512;
constexpr int G_ = 1536;          // 3*H
constexpr int M_ = B_ * L_;       // 32768 rows per direction
constexpr float LN_EPS = 1e-5f;

// Scratch (device globals: allocation-free)
__device__ float g_px[2ull * 32768ull * 1536ull];   // LN3(x @ Wx) per dir
__device__ float g_ph[2 * 64 * 1536];               // per-step h @ Wh
__device__ float g_hT[2 * 512 * 64];                // hidden transposed [dir][k][b]
__device__ unsigned g_cntA[2][8];                   // level-1 barrier counters
__device__ unsigned g_cntR[2];                      // root counters
__device__ unsigned g_gen2[2];                      // generation flags

// ---------------- packed f32x2 helpers ----------------
__device__ __forceinline__ u64 pack2(float x, float y) {
    u64 r; asm("mov.b64 %0,{%1,%2};" : "=l"(r) : "f"(x), "f"(y)); return r;
}
__device__ __forceinline__ void unpack2(float& x, float& y, u64 v) {
    asm("mov.b64 {%0,%1},%2;" : "=f"(x), "=f"(y) : "l"(v));
}
__device__ __forceinline__ void fma2(u64& d, u64 a, u64 b) {
    asm("fma.rn.f32x2 %0,%1,%2,%0;" : "+l"(d) : "l"(a), "l"(b));
}
__device__ __forceinline__ u64 add2(u64 a, u64 b) {
    u64 d; asm("add.rn.f32x2 %0,%1,%2;" : "=l"(d) : "l"(a), "l"(b)); return d;
}
__device__ __forceinline__ float tanh_fast(float x) {
    float y; asm("tanh.approx.f32 %0,%1;" : "=f"(y) : "f"(x)); return y;
}

// ---------------------------------------------------------------------------
// Kernel 1: px = xs @ Wx.  BM=128, BN=128, BK=16, 256 threads.
// 8m x 8n thread tile; n organized as f32x2 pairs, A broadcast + dup.
// ---------------------------------------------------------------------------
__global__ __launch_bounds__(256) void gemm_px_kernel(
    const float* __restrict__ xs,
    const float* __restrict__ Wxf,
    const float* __restrict__ Wxb)
{
    constexpr int BK = 16, LDA = 132;
    __shared__ float As[BK * LDA];     // A transposed [k][m]
    __shared__ float Bs[BK * 128];     // B [k][n]

    const int dir = blockIdx.z;
    const float* W = dir ? Wxb : Wxf;
    const int m0 = blockIdx.y * 128;
    const int n0 = blockIdx.x * 128;
    const int t  = threadIdx.x;
    const int tx = t & 15;
    const int ty = t >> 4;

    u64 acc[8][4];
#pragma unroll
    for (int m = 0; m < 8; m++)
#pragma unroll
        for (int np = 0; np < 4; np++) acc[m][np] = 0ull;

    for (int kt = 0; kt < E_; kt += BK) {
#pragma unroll
        for (int i = 0; i < 2; i++) {
            int idx = t + 256 * i;
            int row = idx >> 2;
            int c4  = idx & 3;
            int m   = m0 + row;
            int b   = m >> 9;
            int s   = m & 511;
            int torig = dir ? (511 - s) : s;
            const float4 va = *reinterpret_cast<const float4*>(
                xs + ((size_t)(b * 512 + torig)) * 512 + kt + c4 * 4);
            As[(c4 * 4 + 0) * LDA + row] = va.x;
            As[(c4 * 4 + 1) * LDA + row] = va.y;
            As[(c4 * 4 + 2) * LDA + row] = va.z;
            As[(c4 * 4 + 3) * LDA + row] = va.w;
        }
#pragma unroll
        for (int i = 0; i < 2; i++) {
            int idx = t + 256 * i;
            int row = idx >> 5;
            int c4  = idx & 31;
            const float4 vb = *reinterpret_cast<const float4*>(
                W + (size_t)(kt + row) * G_ + n0 + c4 * 4);
            *reinterpret_cast<float4*>(Bs + row * 128 + c4 * 4) = vb;
        }
        __syncthreads();

#pragma unroll
        for (int k = 0; k < BK; k++) {
            float4 a0 = *reinterpret_cast<const float4*>(As + k * LDA + ty * 8);
            float4 a1 = *reinterpret_cast<const float4*>(As + k * LDA + ty * 8 + 4);
            u64 ad[8];
            ad[0] = pack2(a0.x, a0.x); ad[1] = pack2(a0.y, a0.y);
            ad[2] = pack2(a0.z, a0.z); ad[3] = pack2(a0.w, a0.w);
            ad[4] = pack2(a1.x, a1.x); ad[5] = pack2(a1.y, a1.y);
            ad[6] = pack2(a1.z, a1.z); ad[7] = pack2(a1.w, a1.w);
            const ulonglong2 q0 = *reinterpret_cast<const ulonglong2*>(Bs + k * 128 + tx * 4);
            const ulonglong2 q1 = *reinterpret_cast<const ulonglong2*>(Bs + k * 128 + 64 + tx * 4);
            u64 bp[4] = {q0.x, q0.y, q1.x, q1.y};
#pragma unroll
            for (int m = 0; m < 8; m++) {
                fma2(acc[m][0], ad[m], bp[0]);
                fma2(acc[m][1], ad[m], bp[1]);
                fma2(acc[m][2], ad[m], bp[2]);
                fma2(acc[m][3], ad[m], bp[3]);
            }
        }
        __syncthreads();
    }

    float* C = g_px + (size_t)dir * M_ * G_;
#pragma unroll
    for (int m = 0; m < 8; m++) {
        float* r = C + (size_t)(m0 + ty * 8 + m) * G_ + n0;
        ulonglong2 s0; s0.x = acc[m][0]; s0.y = acc[m][1];
        ulonglong2 s1; s1.x = acc[m][2]; s1.y = acc[m][3];
        *reinterpret_cast<ulonglong2*>(r + tx * 4)      = s0;
        *reinterpret_cast<ulonglong2*>(r + 64 + tx * 4) = s1;
    }
}

// ---------------------------------------------------------------------------
// Kernel 2: in-place LN3 over g_px.
// ---------------------------------------------------------------------------
__global__ __launch_bounds__(128) void ln3_kernel(
    const float* __restrict__ gf, const float* __restrict__ bf,
    const float* __restrict__ gb, const float* __restrict__ bb)
{
    const int blk   = blockIdx.x;
    const int chunk = blk % 3;
    const int row   = blk / 3;
    const int dir   = row >> 15;
    const float* g  = (dir ? gb : gf) + chunk * 512;
    const float* be = (dir ? bb : bf) + chunk * 512;
    float* p = g_px + (size_t)row * G_ + chunk * 512;

    const int t = threadIdx.x;
    float4 v = reinterpret_cast<float4*>(p)[t];
    float s = v.x + v.y + v.z + v.w;
    float q = v.x * v.x + v.y * v.y + v.z * v.z + v.w * v.w;
#pragma unroll
    for (int o = 16; o > 0; o >>= 1) {
        s += __shfl_down_sync(0xffffffffu, s, o);
        q += __shfl_down_sync(0xffffffffu, q, o);
    }
    __shared__ float ss[4], sq[4];
    __shared__ float st[2];
    const int w = t >> 5, lane = t & 31;
    if (lane == 0) { ss[w] = s; sq[w] = q; }
    __syncthreads();
    if (t == 0) {
        float S = ss[0] + ss[1] + ss[2] + ss[3];
        float Q = sq[0] + sq[1] + sq[2] + sq[3];
        float mu = S * (1.f / 512.f);
        float var = Q * (1.f / 512.f) - mu * mu;
        st[0] = mu;
        st[1] = rsqrtf(var + LN_EPS);
    }
    __syncthreads();
    const float mu = st[0], rs = st[1];
    float4 gv = reinterpret_cast<const float4*>(g)[t];
    float4 bv = reinterpret_cast<const float4*>(be)[t];
    v.x = (v.x - mu) * rs * gv.x + bv.x;
    v.y = (v.y - mu) * rs * gv.y + bv.y;
    v.z = (v.z - mu) * rs * gv.z + bv.z;
    v.w = (v.w - mu) * rs * gv.w + bv.w;
    reinterpret_cast<float4*>(p)[t] = v;
}

// ---------------------------------------------------------------------------
// Kernel 3: persistent recurrence, 128 blocks (1/SM), 256 threads.
// Two-level (8x8) software grid barrier per direction.
// ---------------------------------------------------------------------------
constexpr int SLICE = 24;

__device__ __forceinline__ void gridbar(int dir, int grp)
{
    __syncthreads();
    if (threadIdx.x == 0) {
        unsigned gen = *(volatile unsigned*)&g_gen2[dir];
        __threadfence();
        if (atomicAdd(&g_cntA[dir][grp], 1u) == 7u) {
            g_cntA[dir][grp] = 0u;                       // reset before release
            if (atomicAdd(&g_cntR[dir], 1u) == 7u) {
                g_cntR[dir] = 0u;
                __threadfence();
                *(volatile unsigned*)&g_gen2[dir] = gen + 1u;
            }
        }
        while (*(volatile unsigned*)&g_gen2[dir] == gen) { }
        __threadfence();
    }
    __syncthreads();
}

__device__ __forceinline__ void stage_chunk(const float* gsrc, const float* dst, int t)
{
    unsigned saddr = (unsigned)__cvta_generic_to_shared(dst);
#pragma unroll
    for (int i = 0; i < 8; i++) {
        int off = (t + 256 * i) * 16;
        asm volatile("cp.async.cg.shared.global [%0], [%1], 16;"
                     :: "r"(saddr + off), "l"((const char*)gsrc + off) : "memory");
    }
    asm volatile("cp.async.commit_group;" ::: "memory");
}

__global__ __launch_bounds__(256) void rnn_kernel(
    const float* __restrict__ Whf, const float* __restrict__ Whb,
    const float* __restrict__ ghf, const float* __restrict__ bhf,
    const float* __restrict__ ghb, const float* __restrict__ bhb,
    const float* __restrict__ mask, float* __restrict__ out)
{
    extern __shared__ float smem[];
    float* sWh = smem;                    // [512][32] padded (j-groups of 8: 6 used)
    float* sh  = smem + 512 * 32;         // 2 x (128 k x 64 b) staging buffers
    __shared__ float sred[48];
    __shared__ float sstat[6];

    const int t   = threadIdx.x;
    const int blk = blockIdx.x;
    const int dir = blk >> 6;
    const int sub = blk & 63;             // G: j-slice id. U: batch row.
    const int grp = sub >> 3;             // barrier level-1 group
    const float* Wh = dir ? Whb : Whf;
    const float* gh = dir ? ghb : ghf;
    const float* bh = dir ? bhb : bhf;
    const int j0 = sub * SLICE;

    // G-phase thread decode: q = k-split (within chunk), jg = j-group, bg = b-group
    const int q  = t >> 6;
    const int jg = (t >> 4) & 3;
    const int bg = t & 15;
    const int pos = t & 63;

    // One-time: persistent Wh slice -> SMEM, padded [k][4][8]
    for (int i = t; i < 512 * SLICE; i += 256) {
        int k  = i / SLICE;
        int jj = i - k * SLICE;
        sWh[k * 32 + jj + (jj / 6) * 2] = Wh[(size_t)k * G_ + j0 + jj];
    }
    // One-time: zero this block's hT column range
    for (int i = t; i < 512; i += 256)
        g_hT[dir * 32768 + sub * 512 + i] = 0.f;

    // U-phase constants
    float gg6[6], bb6[6];
#pragma unroll
    for (int i = 0; i < 6; i++) {
        int j = (i >> 1) * 512 + (i & 1) * 256 + t;
        gg6[i] = gh[j];
        bb6[i] = bh[j];
    }
    const float* pxrow = g_px + ((size_t)(dir * 64 + sub)) * ((size_t)L_ * G_);
    const float* hTg = g_hT + dir * 32768;
    float* phd = g_ph + dir * 64 * G_;
    const float* mrow = mask + sub * 512;
    const int wj = t >> 5, lane = t & 31;

    float h0 = 0.f, h1 = 0.f;             // hidden state in registers (cols t, t+256)

    gridbar(dir, grp);                     // hT zeros visible

    for (int s = 0; s < L_; s++) {
        // ---- prefetch U-phase inputs (consumed ~4us later) ----
        const int torig = dir ? (511 - s) : s;
        const float* pxt = pxrow + (size_t)s * G_;
        const float m   = __ldg(mrow + torig);
        const float xz0 = __ldg(pxt + t);
        const float xr0 = __ldg(pxt + 512 + t);
        const float xg0 = __ldg(pxt + 1024 + t);
        const float xz1 = __ldg(pxt + 256 + t);
        const float xr1 = __ldg(pxt + 768 + t);
        const float xg1 = __ldg(pxt + 1280 + t);

        // ---- Phase G: ph[b][j0..j0+23] = sum_k hT[k][b] * Wh[k][j] ----
        u64 a[12];                         // [jp*4 + b] packed (j-even, j-odd)
#pragma unroll
        for (int i = 0; i < 12; i++) a[i] = 0ull;

        stage_chunk(hTg,            sh,        t);   // chunk 0 -> buf0
        stage_chunk(hTg + 128 * 64, sh + 8192, t);   // chunk 1 -> buf1

        for (int c = 0; c < 4; c++) {
            if (c == 3) asm volatile("cp.async.wait_group 0;" ::: "memory");
            else        asm volatile("cp.async.wait_group 1;" ::: "memory");
            __syncthreads();

            const float* shc   = sh + (c & 1) * 8192;
            const float* wbase = sWh + (c * 128 + q * 32) * 32 + jg * 8;
            const float* hbase = shc + (q * 32) * 64 + bg * 4;
#pragma unroll 8
            for (int kk = 0; kk < 32; kk++) {
                const ulonglong2 wp01 = *reinterpret_cast<const ulonglong2*>(wbase + kk * 32);
                const u64 wp2 = *reinterpret_cast<const u64*>(wbase + kk * 32 + 4);
                const float4 hv = *reinterpret_cast<const float4*>(hbase + kk * 64);
                u64 hd0 = pack2(hv.x, hv.x);
                u64 hd1 = pack2(hv.y, hv.y);
                u64 hd2 = pack2(hv.z, hv.z);
                u64 hd3 = pack2(hv.w, hv.w);
                fma2(a[0], wp01.x, hd0); fma2(a[1], wp01.x, hd1);
                fma2(a[2], wp01.x, hd2); fma2(a[3], wp01.x, hd3);
                fma2(a[4], wp01.y, hd0); fma2(a[5], wp01.y, hd1);
                fma2(a[6], wp01.y, hd2); fma2(a[7], wp01.y, hd3);
                fma2(a[8], wp2,    hd0); fma2(a[9], wp2,    hd1);
                fma2(a[10], wp2,   hd2); fma2(a[11], wp2,   hd3);
            }
            __syncthreads();
            if (c < 2)
                stage_chunk(hTg + (c + 2) * 128 * 64, sh + (c & 1) * 8192, t);
        }

        // k-split reduction through buf0 (free now), then write ph
        {
            u64* red = reinterpret_cast<u64*>(sh);
            if (q) {
                u64* r = red + ((q - 1) * 64 + pos) * 12;
#pragma unroll
                for (int i = 0; i < 12; i++) r[i] = a[i];
            }
            __syncthreads();
            if (q == 0) {
#pragma unroll
                for (int w = 0; w < 3; w++) {
                    const u64* r = red + (w * 64 + pos) * 12;
#pragma unroll
                    for (int i = 0; i < 12; i++) a[i] = add2(a[i], r[i]);
                }
                const int jbase = j0 + jg * 6;
#pragma unroll
                for (int b = 0; b < 4; b++) {
                    u64* pr = reinterpret_cast<u64*>(phd + (size_t)(bg * 4 + b) * G_ + jbase);
                    pr[0] = a[b];
                    pr[1] = a[4 + b];
                    pr[2] = a[8 + b];
                }
            }
        }
        gridbar(dir, grp);

        // ---- Phase U: LN3(ph) + GRU gates for batch row `sub` ----
        const float* phr = phd + (size_t)sub * G_;
        float v0 = __ldcg(phr + t);
        float v1 = __ldcg(phr + 256 + t);
        float v2 = __ldcg(phr + 512 + t);
        float v3 = __ldcg(phr + 768 + t);
        float v4 = __ldcg(phr + 1024 + t);
        float v5 = __ldcg(phr + 1280 + t);

        float p0 = v0 + v1, p1 = v2 + v3, p2 = v4 + v5;
        float q0 = v0 * v0 + v1 * v1;
        float q1 = v2 * v2 + v3 * v3;
        float q2 = v4 * v4 + v5 * v5;
#pragma unroll
        for (int o = 16; o > 0; o >>= 1) {
            p0 += __shfl_down_sync(0xffffffffu, p0, o);
            p1 += __shfl_down_sync(0xffffffffu, p1, o);
            p2 += __shfl_down_sync(0xffffffffu, p2, o);
            q0 += __shfl_down_sync(0xffffffffu, q0, o);
            q1 += __shfl_down_sync(0xffffffffu, q1, o);
            q2 += __shfl_down_sync(0xffffffffu, q2, o);
        }
        if (lane == 0) {
            sred[wj * 6 + 0] = p0; sred[wj * 6 + 1] = p1; sred[wj * 6 + 2] = p2;
            sred[wj * 6 + 3] = q0; sred[wj * 6 + 4] = q1; sred[wj * 6 + 5] = q2;
        }
        __syncthreads();
        if (t < 6) {
            float tot = 0.f;
#pragma unroll
            for (int w = 0; w < 8; w++) tot += sred[w * 6 + t];
            sstat[t] = tot;
        }
        __syncthreads();
        const float mu0 = sstat[0] * (1.f / 512.f);
        const float mu1 = sstat[1] * (1.f / 512.f);
        const float mu2 = sstat[2] * (1.f / 512.f);
        const float rs0 = rsqrtf(sstat[3] * (1.f / 512.f) - mu0 * mu0 + LN_EPS);
        const float rs1 = rsqrtf(sstat[4] * (1.f / 512.f) - mu1 * mu1 + LN_EPS);
        const float rs2 = rsqrtf(sstat[5] * (1.f / 512.f) - mu2 * mu2 + LN_EPS);

        float* outt = out + ((size_t)sub * 512 + torig) * 1024 + dir * 512;
        float* hwr = g_hT + dir * 32768;

        // half 0: column t
        {
            float phz  = (v0 - mu0) * rs0 * gg6[0] + bb6[0];
            float phrv = (v2 - mu1) * rs1 * gg6[2] + bb6[2];
            float phgv = (v4 - mu2) * rs2 * gg6[4] + bb6[4];
            float z  = 1.f / (1.f + __expf(-(xz0 + phz)));
            float r  = 1.f / (1.f + __expf(-(xr0 + phrv)));
            float gv = tanh_fast(xg0 + r * phgv);
            h0 = h0 + m * z * (gv - h0);
            hwr[t * 64 + sub] = h0;
            outt[t] = h0 * m;
        }
        // half 1: column t+256
        {
            float phz  = (v1 - mu0) * rs0 * gg6[1] + bb6[1];
            float phrv = (v3 - mu1) * rs1 * gg6[3] + bb6[3];
            float phgv = (v5 - mu2) * rs2 * gg6[5] + bb6[5];
            float z  = 1.f / (1.f + __expf(-(xz1 + phz)));
            float r  = 1.f / (1.f + __expf(-(xr1 + phrv)));
            float gv = tanh_fast(xg1 + r * phgv);
            h1 = h1 + m * z * (gv - h1);
            hwr[(t + 256) * 64 + sub] = h1;
            outt[t + 256] = h1 * m;
        }
        gridbar(dir, grp);
    }
}

// ---------------------------------------------------------------------------
extern "C" void kernel_launch(void* const* d_in, const int* in_sizes, int n_in,
                              void* d_out, int out_size)
{
    const float* xs    = (const float*)d_in[0];
    const float* xmask = (const float*)d_in[1];
    const float* fWx   = (const float*)d_in[2];
    const float* fWh   = (const float*)d_in[3];
    const float* fgx   = (const float*)d_in[4];
    const float* fbx   = (const float*)d_in[5];
    const float* fgh   = (const float*)d_in[6];
    const float* fbh   = (const float*)d_in[7];
    const float* bWx   = (const float*)d_in[8];
    const float* bWh   = (const float*)d_in[9];
    const float* bgx   = (const float*)d_in[10];
    const float* bbx   = (const float*)d_in[11];
    const float* bgh   = (const float*)d_in[12];
    const float* bbh   = (const float*)d_in[13];
    float* out = (float*)d_out;

    // dynamic smem: Wh slice (512*32 floats) + 2 staging buffers (2*128*64)
    const int rnn_smem = (512 * 32 + 2 * 128 * 64) * (int)sizeof(float);  // 131072
    cudaFuncSetAttribute(rnn_kernel, cudaFuncAttributeMaxDynamicSharedMemorySize, rnn_smem);

    // 1) px = xs @ Wx (both directions; dir=1 uses time-reversed xs)
    dim3 ggrid(G_ / 128, M_ / 128, 2);
    gemm_px_kernel<<<ggrid, 256>>>(xs, fWx, bWx);

    // 2) in-place LN3 on px
    ln3_kernel<<<2 * M_ * 3, 128>>>(fgx, fbx, bgx, bbx);

    // 3) persistent bidirectional GRU recurrence
    rnn_kernel<<<128, 256, rnn_smem>>>(fWh, bWh, fgh, fbh, bgh, bbh, xmask, out);
}

// round 11
// speedup vs baseline: 1.1714x; 1.1228x over previous
#include <cuda_runtime.h>
#include <cstdint>
#include <cstddef>

using u64 = unsigned long long;

// Problem constants
constexpr int B_ = 64;
constexpr int L_ = 512;
constexpr int E_ = 512;
constexpr int G_ = 1536;          // 3*H
constexpr int M_ = B_ * L_;       // 32768 rows per direction
constexpr float LN_EPS = 1e-5f;

// Scratch (device globals: allocation-free)
__device__ float g_px[2ull * 32768ull * 1536ull];   // LN3(x @ Wx) per dir
__device__ float g_ph[2 * 64 * 1536];               // per-step h @ Wh
__device__ float g_hT[2 * 512 * 64];                // hidden transposed [dir][k][b]
__device__ unsigned g_cnt2[2];                      // per-dir grid barrier
__device__ unsigned g_gen2[2];

// ---------------- packed f32x2 helpers ----------------
__device__ __forceinline__ u64 pack2(float x, float y) {
    u64 r; asm("mov.b64 %0,{%1,%2};" : "=l"(r) : "f"(x), "f"(y)); return r;
}
__device__ __forceinline__ void fma2(u64& d, u64 a, u64 b) {
    asm("fma.rn.f32x2 %0,%1,%2,%0;" : "+l"(d) : "l"(a), "l"(b));
}
__device__ __forceinline__ u64 add2(u64 a, u64 b) {
    u64 d; asm("add.rn.f32x2 %0,%1,%2;" : "=l"(d) : "l"(a), "l"(b)); return d;
}
__device__ __forceinline__ float tanh_fast(float x) {
    float y; asm("tanh.approx.f32 %0,%1;" : "=f"(y) : "f"(x)); return y;
}

// ---------------------------------------------------------------------------
// Kernel 1: px = xs @ Wx.  BM=128, BN=128, BK=16, 256 threads.
// 8m x 8n thread tile; n organized as f32x2 pairs, A broadcast + dup.
// ---------------------------------------------------------------------------
__global__ __launch_bounds__(256) void gemm_px_kernel(
    const float* __restrict__ xs,
    const float* __restrict__ Wxf,
    const float* __restrict__ Wxb)
{
    constexpr int BK = 16, LDA = 132;
    __shared__ float As[BK * LDA];     // A transposed [k][m]
    __shared__ float Bs[BK * 128];     // B [k][n]

    const int dir = blockIdx.z;
    const float* W = dir ? Wxb : Wxf;
    const int m0 = blockIdx.y * 128;
    const int n0 = blockIdx.x * 128;
    const int t  = threadIdx.x;
    const int tx = t & 15;
    const int ty = t >> 4;

    u64 acc[8][4];
#pragma unroll
    for (int m = 0; m < 8; m++)
#pragma unroll
        for (int np = 0; np < 4; np++) acc[m][np] = 0ull;

    for (int kt = 0; kt < E_; kt += BK) {
#pragma unroll
        for (int i = 0; i < 2; i++) {
            int idx = t + 256 * i;
            int row = idx >> 2;
            int c4  = idx & 3;
            int m   = m0 + row;
            int b   = m >> 9;
            int s   = m & 511;
            int torig = dir ? (511 - s) : s;
            const float4 va = *reinterpret_cast<const float4*>(
                xs + ((size_t)(b * 512 + torig)) * 512 + kt + c4 * 4);
            As[(c4 * 4 + 0) * LDA + row] = va.x;
            As[(c4 * 4 + 1) * LDA + row] = va.y;
            As[(c4 * 4 + 2) * LDA + row] = va.z;
            As[(c4 * 4 + 3) * LDA + row] = va.w;
        }
#pragma unroll
        for (int i = 0; i < 2; i++) {
            int idx = t + 256 * i;
            int row = idx >> 5;
            int c4  = idx & 31;
            const float4 vb = *reinterpret_cast<const float4*>(
                W + (size_t)(kt + row) * G_ + n0 + c4 * 4);
            *reinterpret_cast<float4*>(Bs + row * 128 + c4 * 4) = vb;
        }
        __syncthreads();

#pragma unroll
        for (int k = 0; k < BK; k++) {
            float4 a0 = *reinterpret_cast<const float4*>(As + k * LDA + ty * 8);
            float4 a1 = *reinterpret_cast<const float4*>(As + k * LDA + ty * 8 + 4);
            u64 ad[8];
            ad[0] = pack2(a0.x, a0.x); ad[1] = pack2(a0.y, a0.y);
            ad[2] = pack2(a0.z, a0.z); ad[3] = pack2(a0.w, a0.w);
            ad[4] = pack2(a1.x, a1.x); ad[5] = pack2(a1.y, a1.y);
            ad[6] = pack2(a1.z, a1.z); ad[7] = pack2(a1.w, a1.w);
            const ulonglong2 q0 = *reinterpret_cast<const ulonglong2*>(Bs + k * 128 + tx * 4);
            const ulonglong2 q1 = *reinterpret_cast<const ulonglong2*>(Bs + k * 128 + 64 + tx * 4);
            u64 bp[4] = {q0.x, q0.y, q1.x, q1.y};
#pragma unroll
            for (int m = 0; m < 8; m++) {
                fma2(acc[m][0], ad[m], bp[0]);
                fma2(acc[m][1], ad[m], bp[1]);
                fma2(acc[m][2], ad[m], bp[2]);
                fma2(acc[m][3], ad[m], bp[3]);
            }
        }
        __syncthreads();
    }

    float* C = g_px + (size_t)dir * M_ * G_;
#pragma unroll
    for (int m = 0; m < 8; m++) {
        float* r = C + (size_t)(m0 + ty * 8 + m) * G_ + n0;
        ulonglong2 s0; s0.x = acc[m][0]; s0.y = acc[m][1];
        ulonglong2 s1; s1.x = acc[m][2]; s1.y = acc[m][3];
        *reinterpret_cast<ulonglong2*>(r + tx * 4)      = s0;
        *reinterpret_cast<ulonglong2*>(r + 64 + tx * 4) = s1;
    }
}

// ---------------------------------------------------------------------------
// Kernel 2: in-place LN3 over g_px.
// ---------------------------------------------------------------------------
__global__ __launch_bounds__(128) void ln3_kernel(
    const float* __restrict__ gf, const float* __restrict__ bf,
    const float* __restrict__ gb, const float* __restrict__ bb)
{
    const int blk   = blockIdx.x;
    const int chunk = blk % 3;
    const int row   = blk / 3;
    const int dir   = row >> 15;
    const float* g  = (dir ? gb : gf) + chunk * 512;
    const float* be = (dir ? bb : bf) + chunk * 512;
    float* p = g_px + (size_t)row * G_ + chunk * 512;

    const int t = threadIdx.x;
    float4 v = reinterpret_cast<float4*>(p)[t];
    float s = v.x + v.y + v.z + v.w;
    float q = v.x * v.x + v.y * v.y + v.z * v.z + v.w * v.w;
#pragma unroll
    for (int o = 16; o > 0; o >>= 1) {
        s += __shfl_down_sync(0xffffffffu, s, o);
        q += __shfl_down_sync(0xffffffffu, q, o);
    }
    __shared__ float ss[4], sq[4];
    __shared__ float st[2];
    const int w = t >> 5, lane = t & 31;
    if (lane == 0) { ss[w] = s; sq[w] = q; }
    __syncthreads();
    if (t == 0) {
        float S = ss[0] + ss[1] + ss[2] + ss[3];
        float Q = sq[0] + sq[1] + sq[2] + sq[3];
        float mu = S * (1.f / 512.f);
        float var = Q * (1.f / 512.f) - mu * mu;
        st[0] = mu;
        st[1] = rsqrtf(var + LN_EPS);
    }
    __syncthreads();
    const float mu = st[0], rs = st[1];
    float4 gv = reinterpret_cast<const float4*>(g)[t];
    float4 bv = reinterpret_cast<const float4*>(be)[t];
    v.x = (v.x - mu) * rs * gv.x + bv.x;
    v.y = (v.y - mu) * rs * gv.y + bv.y;
    v.z = (v.z - mu) * rs * gv.z + bv.z;
    v.w = (v.w - mu) * rs * gv.w + bv.w;
    reinterpret_cast<float4*>(p)[t] = v;
}

// ---------------------------------------------------------------------------
// Kernel 3: persistent recurrence, 128 blocks (1/SM), 256 threads.
// Single-level per-direction barrier with nanosleep backoff (proven best).
// ---------------------------------------------------------------------------
constexpr int SLICE = 24;

__device__ __forceinline__ void gridbar(int dir)
{
    __syncthreads();
    if (threadIdx.x == 0) {
        unsigned gen = *(volatile unsigned*)&g_gen2[dir];
        __threadfence();
        if (atomicAdd(&g_cnt2[dir], 1u) == 63u) {
            g_cnt2[dir] = 0u;
            __threadfence();
            *(volatile unsigned*)&g_gen2[dir] = gen + 1u;
        } else {
            while (*(volatile unsigned*)&g_gen2[dir] == gen) { __nanosleep(32); }
            __threadfence();
        }
    }
    __syncthreads();
}

__device__ __forceinline__ void stage_chunk(const float* gsrc, const float* dst, int t)
{
    unsigned saddr = (unsigned)__cvta_generic_to_shared(dst);
#pragma unroll
    for (int i = 0; i < 8; i++) {
        int off = (t + 256 * i) * 16;
        asm volatile("cp.async.cg.shared.global [%0], [%1], 16;"
                     :: "r"(saddr + off), "l"((const char*)gsrc + off) : "memory");
    }
    asm volatile("cp.async.commit_group;" ::: "memory");
}

__global__ __launch_bounds__(256) void rnn_kernel(
    const float* __restrict__ Whf, const float* __restrict__ Whb,
    const float* __restrict__ ghf, const float* __restrict__ bhf,
    const float* __restrict__ ghb, const float* __restrict__ bhb,
    const float* __restrict__ mask, float* __restrict__ out)
{
    extern __shared__ float smem[];
    float* sWh = smem;                    // [512][32] padded (j-groups of 8: 6 used)
    float* sh  = smem + 512 * 32;         // 2 x (128 k x 64 b) staging buffers
    __shared__ float sred[48];
    __shared__ float sstat[6];

    const int t   = threadIdx.x;
    const int blk = blockIdx.x;
    const int dir = blk >> 6;
    const int sub = blk & 63;             // G: j-slice id. U: batch row.
    const float* Wh = dir ? Whb : Whf;
    const float* gh = dir ? ghb : ghf;
    const float* bh = dir ? bhb : bhf;
    const int j0 = sub * SLICE;

    // G-phase thread decode: q = k-split (within chunk), jg = j-group, bg = b-group
    const int q  = t >> 6;
    const int jg = (t >> 4) & 3;
    const int bg = t & 15;
    const int pos = t & 63;

    // One-time: persistent Wh slice -> SMEM, padded [k][4][8]
    for (int i = t; i < 512 * SLICE; i += 256) {
        int k  = i / SLICE;
        int jj = i - k * SLICE;
        sWh[k * 32 + jj + (jj / 6) * 2] = Wh[(size_t)k * G_ + j0 + jj];
    }
    // One-time: zero this block's hT column range
    for (int i = t; i < 512; i += 256)
        g_hT[dir * 32768 + sub * 512 + i] = 0.f;

    // U-phase constants
    float gg6[6], bb6[6];
#pragma unroll
    for (int i = 0; i < 6; i++) {
        int j = (i >> 1) * 512 + (i & 1) * 256 + t;
        gg6[i] = gh[j];
        bb6[i] = bh[j];
    }
    const float* pxrow = g_px + ((size_t)(dir * 64 + sub)) * ((size_t)L_ * G_);
    const float* hTg = g_hT + dir * 32768;
    float* phd = g_ph + dir * 64 * G_;
    const float* mrow = mask + sub * 512;
    const int wj = t >> 5, lane = t & 31;

    float h0 = 0.f, h1 = 0.f;             // hidden state in registers (cols t, t+256)

    // software-pipelined U-phase inputs (prefetched one step ahead)
    float n_m, n_xz0, n_xr0, n_xg0, n_xz1, n_xr1, n_xg1;
    {
        const int t0 = dir ? 511 : 0;
        const float* npx = pxrow;        // s = 0
        n_m   = __ldg(mrow + t0);
        n_xz0 = __ldg(npx + t);        n_xz1 = __ldg(npx + 256 + t);
        n_xr0 = __ldg(npx + 512 + t);  n_xr1 = __ldg(npx + 768 + t);
        n_xg0 = __ldg(npx + 1024 + t); n_xg1 = __ldg(npx + 1280 + t);
    }

    gridbar(dir);                          // hT zeros visible

    for (int s = 0; s < L_; s++) {
        const int torig = dir ? (511 - s) : s;
        const float m = n_m;
        const float xz0 = n_xz0, xr0 = n_xr0, xg0 = n_xg0;
        const float xz1 = n_xz1, xr1 = n_xr1, xg1 = n_xg1;

        // ---- Phase G: ph[b][j0..j0+23] = sum_k hT[k][b] * Wh[k][j] ----
        u64 a[12];                         // [jp*4 + b] packed (j-even, j-odd)
#pragma unroll
        for (int i = 0; i < 12; i++) a[i] = 0ull;

        stage_chunk(hTg,            sh,        t);   // chunk 0 -> buf0
        stage_chunk(hTg + 128 * 64, sh + 8192, t);   // chunk 1 -> buf1

        for (int c = 0; c < 4; c++) {
            if (c == 3) asm volatile("cp.async.wait_group 0;" ::: "memory");
            else        asm volatile("cp.async.wait_group 1;" ::: "memory");
            __syncthreads();

            const float* shc   = sh + (c & 1) * 8192;
            const float* wbase = sWh + (c * 128 + q * 32) * 32 + jg * 8;
            const float* hbase = shc + (q * 32) * 64 + bg * 4;
#pragma unroll 8
            for (int kk = 0; kk < 32; kk++) {
                const ulonglong2 wp01 = *reinterpret_cast<const ulonglong2*>(wbase + kk * 32);
                const u64 wp2 = *reinterpret_cast<const u64*>(wbase + kk * 32 + 4);
                const float4 hv = *reinterpret_cast<const float4*>(hbase + kk * 64);
                u64 hd0 = pack2(hv.x, hv.x);
                u64 hd1 = pack2(hv.y, hv.y);
                u64 hd2 = pack2(hv.z, hv.z);
                u64 hd3 = pack2(hv.w, hv.w);
                fma2(a[0], wp01.x, hd0); fma2(a[1], wp01.x, hd1);
                fma2(a[2], wp01.x, hd2); fma2(a[3], wp01.x, hd3);
                fma2(a[4], wp01.y, hd0); fma2(a[5], wp01.y, hd1);
                fma2(a[6], wp01.y, hd2); fma2(a[7], wp01.y, hd3);
                fma2(a[8], wp2,    hd0); fma2(a[9], wp2,    hd1);
                fma2(a[10], wp2,   hd2); fma2(a[11], wp2,   hd3);
            }
            __syncthreads();
            if (c < 2)
                stage_chunk(hTg + (c + 2) * 128 * 64, sh + (c & 1) * 8192, t);
        }

        // k-split reduction through buf0 (free now), then write ph
        {
            u64* red = reinterpret_cast<u64*>(sh);
            if (q) {
                u64* r = red + ((q - 1) * 64 + pos) * 12;
#pragma unroll
                for (int i = 0; i < 12; i++) r[i] = a[i];
            }
            __syncthreads();
            if (q == 0) {
#pragma unroll
                for (int w = 0; w < 3; w++) {
                    const u64* r = red + (w * 64 + pos) * 12;
#pragma unroll
                    for (int i = 0; i < 12; i++) a[i] = add2(a[i], r[i]);
                }
                const int jbase = j0 + jg * 6;
#pragma unroll
                for (int b = 0; b < 4; b++) {
                    u64* pr = reinterpret_cast<u64*>(phd + (size_t)(bg * 4 + b) * G_ + jbase);
                    pr[0] = a[b];
                    pr[1] = a[4 + b];
                    pr[2] = a[8 + b];
                }
            }
        }
        gridbar(dir);

        // ---- Phase U: LN3(ph) + GRU gates for batch row `sub` ----
        const float* phr = phd + (size_t)sub * G_;
        float v0 = __ldcg(phr + t);
        float v1 = __ldcg(phr + 256 + t);
        float v2 = __ldcg(phr + 512 + t);
        float v3 = __ldcg(phr + 768 + t);
        float v4 = __ldcg(phr + 1024 + t);
        float v5 = __ldcg(phr + 1280 + t);

        float p0 = v0 + v1, p1 = v2 + v3, p2 = v4 + v5;
        float q0 = v0 * v0 + v1 * v1;
        float q1 = v2 * v2 + v3 * v3;
        float q2 = v4 * v4 + v5 * v5;
#pragma unroll
        for (int o = 16; o > 0; o >>= 1) {
            p0 += __shfl_down_sync(0xffffffffu, p0, o);
            p1 += __shfl_down_sync(0xffffffffu, p1, o);
            p2 += __shfl_down_sync(0xffffffffu, p2, o);
            q0 += __shfl_down_sync(0xffffffffu, q0, o);
            q1 += __shfl_down_sync(0xffffffffu, q1, o);
            q2 += __shfl_down_sync(0xffffffffu, q2, o);
        }
        if (lane == 0) {
            sred[wj * 6 + 0] = p0; sred[wj * 6 + 1] = p1; sred[wj * 6 + 2] = p2;
            sred[wj * 6 + 3] = q0; sred[wj * 6 + 4] = q1; sred[wj * 6 + 5] = q2;
        }
        __syncthreads();
        if (t < 6) {
            float tot = 0.f;
#pragma unroll
            for (int w = 0; w < 8; w++) tot += sred[w * 6 + t];
            sstat[t] = tot;
        }
        __syncthreads();
        const float mu0 = sstat[0] * (1.f / 512.f);
        const float mu1 = sstat[1] * (1.f / 512.f);
        const float mu2 = sstat[2] * (1.f / 512.f);
        const float rs0 = rsqrtf(sstat[3] * (1.f / 512.f) - mu0 * mu0 + LN_EPS);
        const float rs1 = rsqrtf(sstat[4] * (1.f / 512.f) - mu1 * mu1 + LN_EPS);
        const float rs2 = rsqrtf(sstat[5] * (1.f / 512.f) - mu2 * mu2 + LN_EPS);

        float* outt = out + ((size_t)sub * 512 + torig) * 1024 + dir * 512;
        float* hwr = g_hT + dir * 32768;

        float o0, o1;
        // half 0: column t
        {
            float phz  = (v0 - mu0) * rs0 * gg6[0] + bb6[0];
            float phrv = (v2 - mu1) * rs1 * gg6[2] + bb6[2];
            float phgv = (v4 - mu2) * rs2 * gg6[4] + bb6[4];
            float z  = 1.f / (1.f + __expf(-(xz0 + phz)));
            float r  = 1.f / (1.f + __expf(-(xr0 + phrv)));
            float gv = tanh_fast(xg0 + r * phgv);
            h0 = h0 + m * z * (gv - h0);
            hwr[t * 64 + sub] = h0;
            o0 = h0 * m;
        }
        // half 1: column t+256
        {
            float phz  = (v1 - mu0) * rs0 * gg6[1] + bb6[1];
            float phrv = (v3 - mu1) * rs1 * gg6[3] + bb6[3];
            float phgv = (v5 - mu2) * rs2 * gg6[5] + bb6[5];
            float z  = 1.f / (1.f + __expf(-(xz1 + phz)));
            float r  = 1.f / (1.f + __expf(-(xr1 + phrv)));
            float gv = tanh_fast(xg1 + r * phgv);
            h1 = h1 + m * z * (gv - h1);
            hwr[(t + 256) * 64 + sub] = h1;
            o1 = h1 * m;
        }

        // ---- bar2: arrive early; overlap out-stores + next-step prefetch ----
        __syncthreads();                    // hT stores complete block-wide
        unsigned genl = 0;
        bool released = false;
        if (t == 0) {
            genl = *(volatile unsigned*)&g_gen2[dir];
            __threadfence();                // publish hT
            if (atomicAdd(&g_cnt2[dir], 1u) == 63u) {
                g_cnt2[dir] = 0u;
                __threadfence();
                *(volatile unsigned*)&g_gen2[dir] = genl + 1u;
                released = true;
            }
        }
        // overlapped work (not ordered by the barrier):
        outt[t]       = o0;
        outt[t + 256] = o1;
        if (s + 1 < L_) {
            const int nto = dir ? (510 - s) : (s + 1);
            const float* npx = pxrow + (size_t)(s + 1) * G_;
            n_m   = __ldg(mrow + nto);
            n_xz0 = __ldg(npx + t);        n_xz1 = __ldg(npx + 256 + t);
            n_xr0 = __ldg(npx + 512 + t);  n_xr1 = __ldg(npx + 768 + t);
            n_xg0 = __ldg(npx + 1024 + t); n_xg1 = __ldg(npx + 1280 + t);
        }
        if (t == 0 && !released) {
            while (*(volatile unsigned*)&g_gen2[dir] == genl) { __nanosleep(32); }
            __threadfence();
        }
        __syncthreads();
    }
}

// ---------------------------------------------------------------------------
extern "C" void kernel_launch(void* const* d_in, const int* in_sizes, int n_in,
                              void* d_out, int out_size)
{
    const float* xs    = (const float*)d_in[0];
    const float* xmask = (const float*)d_in[1];
    const float* fWx   = (const float*)d_in[2];
    const float* fWh   = (const float*)d_in[3];
    const float* fgx   = (const float*)d_in[4];
    const float* fbx   = (const float*)d_in[5];
    const float* fgh   = (const float*)d_in[6];
    const float* fbh   = (const float*)d_in[7];
    const float* bWx   = (const float*)d_in[8];
    const float* bWh   = (const float*)d_in[9];
    const float* bgx   = (const float*)d_in[10];
    const float* bbx   = (const float*)d_in[11];
    const float* bgh   = (const float*)d_in[12];
    const float* bbh   = (const float*)d_in[13];
    float* out = (float*)d_out;

    // dynamic smem: Wh slice (512*32 floats) + 2 staging buffers (2*128*64)
    const int rnn_smem = (512 * 32 + 2 * 128 * 64) * (int)sizeof(float);  // 131072
    cudaFuncSetAttribute(rnn_kernel, cudaFuncAttributeMaxDynamicSharedMemorySize, rnn_smem);

    // 1) px = xs @ Wx (both directions; dir=1 uses time-reversed xs)
    dim3 ggrid(G_ / 128, M_ / 128, 2);
    gemm_px_kernel<<<ggrid, 256>>>(xs, fWx, bWx);

    // 2) in-place LN3 on px
    ln3_kernel<<<2 * M_ * 3, 128>>>(fgx, fbx, bgx, bbx);

    // 3) persistent bidirectional GRU recurrence
    rnn_kernel<<<128, 256, rnn_smem>>>(fWh, bWh, fgh, fbh, bgh, bbh, xmask, out);
}

// round 12
// speedup vs baseline: 1.1837x; 1.0105x over previous
#include <cuda_runtime.h>
#include <cstdint>
#include <cstddef>

using u64 = unsigned long long;

// Problem constants
constexpr int B_ = 64;
constexpr int L_ = 512;
constexpr int E_ = 512;
constexpr int G_ = 1536;          // 3*H
constexpr int M_ = B_ * L_;       // 32768 rows per direction
constexpr float LN_EPS = 1e-5f;

// Scratch (device globals: allocation-free)
__device__ float g_px[2ull * 32768ull * 1536ull];   // LN3(x @ Wx) per dir
__device__ float g_ph[2 * 64 * 1536];               // per-step h @ Wh
__device__ float g_hT[2 * 512 * 64];                // hidden transposed [dir][k][b]
__device__ unsigned g_cnt2[2];                      // per-dir grid barrier
__device__ unsigned g_gen2[2];

// ---------------- packed f32x2 / fast-math helpers ----------------
__device__ __forceinline__ u64 pack2(float x, float y) {
    u64 r; asm("mov.b64 %0,{%1,%2};" : "=l"(r) : "f"(x), "f"(y)); return r;
}
__device__ __forceinline__ void fma2(u64& d, u64 a, u64 b) {
    asm("fma.rn.f32x2 %0,%1,%2,%0;" : "+l"(d) : "l"(a), "l"(b));
}
__device__ __forceinline__ u64 add2(u64 a, u64 b) {
    u64 d; asm("add.rn.f32x2 %0,%1,%2;" : "=l"(d) : "l"(a), "l"(b)); return d;
}
__device__ __forceinline__ float tanh_fast(float x) {
    float y; asm("tanh.approx.f32 %0,%1;" : "=f"(y) : "f"(x)); return y;
}
__device__ __forceinline__ float sig_fast(float x) {
    return 0.5f + 0.5f * tanh_fast(0.5f * x);
}

// ---------------------------------------------------------------------------
// Kernel 1: px = xs @ Wx.  BM=128, BN=128, BK=16, 256 threads.
// 8m x 8n thread tile, n as f32x2 pairs; register-pipelined global loads.
// ---------------------------------------------------------------------------
__global__ __launch_bounds__(256, 2) void gemm_px_kernel(
    const float* __restrict__ xs,
    const float* __restrict__ Wxf,
    const float* __restrict__ Wxb)
{
    constexpr int BK = 16, LDA = 132;
    __shared__ float As[BK * LDA];     // A transposed [k][m]
    __shared__ float Bs[BK * 128];     // B [k][n]

    const int dir = blockIdx.z;
    const float* W = dir ? Wxb : Wxf;
    const int m0 = blockIdx.y * 128;
    const int n0 = blockIdx.x * 128;
    const int t  = threadIdx.x;
    const int tx = t & 15;
    const int ty = t >> 4;

    // Hoisted addressing for the two A / two B fragments this thread loads.
    const float* apx[2];
    int arow[2], ac4[2];
    const float* bpx[2];
    int brow[2], bc4[2];
#pragma unroll
    for (int i = 0; i < 2; i++) {
        int idx = t + 256 * i;
        arow[i] = idx >> 2;
        ac4[i]  = idx & 3;
        int m   = m0 + arow[i];
        int b   = m >> 9;
        int s   = m & 511;
        int torig = dir ? (511 - s) : s;
        apx[i] = xs + ((size_t)(b * 512 + torig)) * 512 + ac4[i] * 4;
        brow[i] = idx >> 5;
        bc4[i]  = idx & 31;
        bpx[i]  = W + (size_t)brow[i] * G_ + n0 + bc4[i] * 4;
    }

    u64 acc[8][4];
#pragma unroll
    for (int m = 0; m < 8; m++)
#pragma unroll
        for (int np = 0; np < 4; np++) acc[m][np] = 0ull;

    // prologue: load tile kt=0 into registers
    float4 rA[2], rB[2];
#pragma unroll
    for (int i = 0; i < 2; i++) {
        rA[i] = *reinterpret_cast<const float4*>(apx[i]);
        rB[i] = *reinterpret_cast<const float4*>(bpx[i]);
    }

    for (int kt = 0; kt < E_; kt += BK) {
        // store current registers to SMEM (A transposed)
#pragma unroll
        for (int i = 0; i < 2; i++) {
            As[(ac4[i] * 4 + 0) * LDA + arow[i]] = rA[i].x;
            As[(ac4[i] * 4 + 1) * LDA + arow[i]] = rA[i].y;
            As[(ac4[i] * 4 + 2) * LDA + arow[i]] = rA[i].z;
            As[(ac4[i] * 4 + 3) * LDA + arow[i]] = rA[i].w;
            *reinterpret_cast<float4*>(Bs + brow[i] * 128 + bc4[i] * 4) = rB[i];
        }
        __syncthreads();

        // kick next tile's loads; they complete while we compute
        if (kt + BK < E_) {
#pragma unroll
            for (int i = 0; i < 2; i++) {
                rA[i] = *reinterpret_cast<const float4*>(apx[i] + kt + BK);
                rB[i] = *reinterpret_cast<const float4*>(bpx[i] + (size_t)(kt + BK) * G_);
            }
        }

#pragma unroll
        for (int k = 0; k < BK; k++) {
            float4 a0 = *reinterpret_cast<const float4*>(As + k * LDA + ty * 8);
            float4 a1 = *reinterpret_cast<const float4*>(As + k * LDA + ty * 8 + 4);
            u64 ad[8];
            ad[0] = pack2(a0.x, a0.x); ad[1] = pack2(a0.y, a0.y);
            ad[2] = pack2(a0.z, a0.z); ad[3] = pack2(a0.w, a0.w);
            ad[4] = pack2(a1.x, a1.x); ad[5] = pack2(a1.y, a1.y);
            ad[6] = pack2(a1.z, a1.z); ad[7] = pack2(a1.w, a1.w);
            const ulonglong2 q0 = *reinterpret_cast<const ulonglong2*>(Bs + k * 128 + tx * 4);
            const ulonglong2 q1 = *reinterpret_cast<const ulonglong2*>(Bs + k * 128 + 64 + tx * 4);
            u64 bp[4] = {q0.x, q0.y, q1.x, q1.y};
#pragma unroll
            for (int m = 0; m < 8; m++) {
                fma2(acc[m][0], ad[m], bp[0]);
                fma2(acc[m][1], ad[m], bp[1]);
                fma2(acc[m][2], ad[m], bp[2]);
                fma2(acc[m][3], ad[m], bp[3]);
            }
        }
        __syncthreads();
    }

    float* C = g_px + (size_t)dir * M_ * G_;
#pragma unroll
    for (int m = 0; m < 8; m++) {
        float* r = C + (size_t)(m0 + ty * 8 + m) * G_ + n0;
        ulonglong2 s0; s0.x = acc[m][0]; s0.y = acc[m][1];
        ulonglong2 s1; s1.x = acc[m][2]; s1.y = acc[m][3];
        *reinterpret_cast<ulonglong2*>(r + tx * 4)      = s0;
        *reinterpret_cast<ulonglong2*>(r + 64 + tx * 4) = s1;
    }
}

// ---------------------------------------------------------------------------
// Kernel 2: in-place LN3 over g_px. Warp-per-chunk (512 floats), 8 warps/block.
// ---------------------------------------------------------------------------
__global__ __launch_bounds__(256) void ln3_kernel(
    const float* __restrict__ gf, const float* __restrict__ bf,
    const float* __restrict__ gb, const float* __restrict__ bb)
{
    const int w    = threadIdx.x >> 5;
    const int lane = threadIdx.x & 31;
    const int gidx = blockIdx.x * 8 + w;          // chunk id 0 .. 2*M*3-1
    const int chunk = gidx % 3;
    const int row   = gidx / 3;
    const int dir   = row >> 15;
    const float* g  = (dir ? gb : gf) + chunk * 512;
    const float* be = (dir ? bb : bf) + chunk * 512;
    float* p = g_px + (size_t)row * G_ + chunk * 512;

    float4 v[4];
#pragma unroll
    for (int i = 0; i < 4; i++)
        v[i] = reinterpret_cast<float4*>(p)[lane + 32 * i];

    float s = 0.f, q = 0.f;
#pragma unroll
    for (int i = 0; i < 4; i++) {
        s += v[i].x + v[i].y + v[i].z + v[i].w;
        q += v[i].x * v[i].x + v[i].y * v[i].y + v[i].z * v[i].z + v[i].w * v[i].w;
    }
#pragma unroll
    for (int o = 16; o > 0; o >>= 1) {
        s += __shfl_xor_sync(0xffffffffu, s, o);
        q += __shfl_xor_sync(0xffffffffu, q, o);
    }
    const float mu = s * (1.f / 512.f);
    const float rs = rsqrtf(q * (1.f / 512.f) - mu * mu + LN_EPS);

#pragma unroll
    for (int i = 0; i < 4; i++) {
        float4 gv = reinterpret_cast<const float4*>(g)[lane + 32 * i];
        float4 bv = reinterpret_cast<const float4*>(be)[lane + 32 * i];
        float4 o;
        o.x = (v[i].x - mu) * rs * gv.x + bv.x;
        o.y = (v[i].y - mu) * rs * gv.y + bv.y;
        o.z = (v[i].z - mu) * rs * gv.z + bv.z;
        o.w = (v[i].w - mu) * rs * gv.w + bv.w;
        reinterpret_cast<float4*>(p)[lane + 32 * i] = o;
    }
}

// ---------------------------------------------------------------------------
// Kernel 3: persistent recurrence, 128 blocks (1/SM), 256 threads.
// Single-level per-direction barrier with nanosleep backoff (proven best).
// ---------------------------------------------------------------------------
constexpr int SLICE = 24;

__device__ __forceinline__ void gridbar(int dir)
{
    __syncthreads();
    if (threadIdx.x == 0) {
        unsigned gen = *(volatile unsigned*)&g_gen2[dir];
        __threadfence();
        if (atomicAdd(&g_cnt2[dir], 1u) == 63u) {
            g_cnt2[dir] = 0u;
            __threadfence();
            *(volatile unsigned*)&g_gen2[dir] = gen + 1u;
        } else {
            while (*(volatile unsigned*)&g_gen2[dir] == gen) { __nanosleep(32); }
            __threadfence();
        }
    }
    __syncthreads();
}

__device__ __forceinline__ void stage_chunk(const float* gsrc, const float* dst, int t)
{
    unsigned saddr = (unsigned)__cvta_generic_to_shared(dst);
#pragma unroll
    for (int i = 0; i < 8; i++) {
        int off = (t + 256 * i) * 16;
        asm volatile("cp.async.cg.shared.global [%0], [%1], 16;"
                     :: "r"(saddr + off), "l"((const char*)gsrc + off) : "memory");
    }
    asm volatile("cp.async.commit_group;" ::: "memory");
}

__global__ __launch_bounds__(256) void rnn_kernel(
    const float* __restrict__ Whf, const float* __restrict__ Whb,
    const float* __restrict__ ghf, const float* __restrict__ bhf,
    const float* __restrict__ ghb, const float* __restrict__ bhb,
    const float* __restrict__ mask, float* __restrict__ out)
{
    extern __shared__ float smem[];
    float* sWh = smem;                    // [512][32] padded (j-groups of 8: 6 used)
    float* sh  = smem + 512 * 32;         // 2 x (128 k x 64 b) staging buffers
    __shared__ float sred[48];
    __shared__ float sstat[6];

    const int t   = threadIdx.x;
    const int blk = blockIdx.x;
    const int dir = blk >> 6;
    const int sub = blk & 63;             // G: j-slice id. U: batch row.
    const float* Wh = dir ? Whb : Whf;
    const float* gh = dir ? ghb : ghf;
    const float* bh = dir ? bhb : bhf;
    const int j0 = sub * SLICE;

    // G-phase thread decode: q = k-split (within chunk), jg = j-group, bg = b-group
    const int q  = t >> 6;
    const int jg = (t >> 4) & 3;
    const int bg = t & 15;
    const int pos = t & 63;

    // One-time: persistent Wh slice -> SMEM, padded [k][4][8]
    for (int i = t; i < 512 * SLICE; i += 256) {
        int k  = i / SLICE;
        int jj = i - k * SLICE;
        sWh[k * 32 + jj + (jj / 6) * 2] = Wh[(size_t)k * G_ + j0 + jj];
    }
    // One-time: zero this block's hT column range
    for (int i = t; i < 512; i += 256)
        g_hT[dir * 32768 + sub * 512 + i] = 0.f;

    // U-phase constants
    float gg6[6], bb6[6];
#pragma unroll
    for (int i = 0; i < 6; i++) {
        int j = (i >> 1) * 512 + (i & 1) * 256 + t;
        gg6[i] = gh[j];
        bb6[i] = bh[j];
    }
    const float* pxrow = g_px + ((size_t)(dir * 64 + sub)) * ((size_t)L_ * G_);
    const float* hTg = g_hT + dir * 32768;
    float* phd = g_ph + dir * 64 * G_;
    const float* mrow = mask + sub * 512;
    const int wj = t >> 5, lane = t & 31;

    float h0 = 0.f, h1 = 0.f;             // hidden state in registers (cols t, t+256)

    // software-pipelined U-phase inputs (prefetched one step ahead)
    float n_m, n_xz0, n_xr0, n_xg0, n_xz1, n_xr1, n_xg1;
    {
        const int t0 = dir ? 511 : 0;
        const float* npx = pxrow;        // s = 0
        n_m   = __ldg(mrow + t0);
        n_xz0 = __ldg(npx + t);        n_xz1 = __ldg(npx + 256 + t);
        n_xr0 = __ldg(npx + 512 + t);  n_xr1 = __ldg(npx + 768 + t);
        n_xg0 = __ldg(npx + 1024 + t); n_xg1 = __ldg(npx + 1280 + t);
    }

    gridbar(dir);                          // hT zeros visible

    for (int s = 0; s < L_; s++) {
        const int torig = dir ? (511 - s) : s;
        const float m = n_m;
        const float xz0 = n_xz0, xr0 = n_xr0, xg0 = n_xg0;
        const float xz1 = n_xz1, xr1 = n_xr1, xg1 = n_xg1;

        // ---- Phase G: ph[b][j0..j0+23] = sum_k hT[k][b] * Wh[k][j] ----
        u64 a[12];                         // [jp*4 + b] packed (j-even, j-odd)
#pragma unroll
        for (int i = 0; i < 12; i++) a[i] = 0ull;

        stage_chunk(hTg,            sh,        t);   // chunk 0 -> buf0
        stage_chunk(hTg + 128 * 64, sh + 8192, t);   // chunk 1 -> buf1

        for (int c = 0; c < 4; c++) {
            if (c == 3) asm volatile("cp.async.wait_group 0;" ::: "memory");
            else        asm volatile("cp.async.wait_group 1;" ::: "memory");
            __syncthreads();

            const float* shc   = sh + (c & 1) * 8192;
            const float* wbase = sWh + (c * 128 + q * 32) * 32 + jg * 8;
            const float* hbase = shc + (q * 32) * 64 + bg * 4;
#pragma unroll 8
            for (int kk = 0; kk < 32; kk++) {
                const ulonglong2 wp01 = *reinterpret_cast<const ulonglong2*>(wbase + kk * 32);
                const u64 wp2 = *reinterpret_cast<const u64*>(wbase + kk * 32 + 4);
                const float4 hv = *reinterpret_cast<const float4*>(hbase + kk * 64);
                u64 hd0 = pack2(hv.x, hv.x);
                u64 hd1 = pack2(hv.y, hv.y);
                u64 hd2 = pack2(hv.z, hv.z);
                u64 hd3 = pack2(hv.w, hv.w);
                fma2(a[0], wp01.x, hd0); fma2(a[1], wp01.x, hd1);
                fma2(a[2], wp01.x, hd2); fma2(a[3], wp01.x, hd3);
                fma2(a[4], wp01.y, hd0); fma2(a[5], wp01.y, hd1);
                fma2(a[6], wp01.y, hd2); fma2(a[7], wp01.y, hd3);
                fma2(a[8], wp2,    hd0); fma2(a[9], wp2,    hd1);
                fma2(a[10], wp2,   hd2); fma2(a[11], wp2,   hd3);
            }
            __syncthreads();
            if (c < 2)
                stage_chunk(hTg + (c + 2) * 128 * 64, sh + (c & 1) * 8192, t);
        }

        // k-split reduction through buf0 (free now), then write ph
        {
            u64* red = reinterpret_cast<u64*>(sh);
            if (q) {
                u64* r = red + ((q - 1) * 64 + pos) * 12;
#pragma unroll
                for (int i = 0; i < 12; i++) r[i] = a[i];
            }
            __syncthreads();
            if (q == 0) {
#pragma unroll
                for (int w = 0; w < 3; w++) {
                    const u64* r = red + (w * 64 + pos) * 12;
#pragma unroll
                    for (int i = 0; i < 12; i++) a[i] = add2(a[i], r[i]);
                }
                const int jbase = j0 + jg * 6;
#pragma unroll
                for (int b = 0; b < 4; b++) {
                    u64* pr = reinterpret_cast<u64*>(phd + (size_t)(bg * 4 + b) * G_ + jbase);
                    pr[0] = a[b];
                    pr[1] = a[4 + b];
                    pr[2] = a[8 + b];
                }
            }
        }
        gridbar(dir);

        // ---- Phase U: LN3(ph) + GRU gates for batch row `sub` ----
        const float* phr = phd + (size_t)sub * G_;
        float v0 = __ldcg(phr + t);
        float v1 = __ldcg(phr + 256 + t);
        float v2 = __ldcg(phr + 512 + t);
        float v3 = __ldcg(phr + 768 + t);
        float v4 = __ldcg(phr + 1024 + t);
        float v5 = __ldcg(phr + 1280 + t);

        float p0 = v0 + v1, p1 = v2 + v3, p2 = v4 + v5;
        float q0 = v0 * v0 + v1 * v1;
        float q1 = v2 * v2 + v3 * v3;
        float q2 = v4 * v4 + v5 * v5;
#pragma unroll
        for (int o = 16; o > 0; o >>= 1) {
            p0 += __shfl_down_sync(0xffffffffu, p0, o);
            p1 += __shfl_down_sync(0xffffffffu, p1, o);
            p2 += __shfl_down_sync(0xffffffffu, p2, o);
            q0 += __shfl_down_sync(0xffffffffu, q0, o);
            q1 += __shfl_down_sync(0xffffffffu, q1, o);
            q2 += __shfl_down_sync(0xffffffffu, q2, o);
        }
        if (lane == 0) {
            sred[wj * 6 + 0] = p0; sred[wj * 6 + 1] = p1; sred[wj * 6 + 2] = p2;
            sred[wj * 6 + 3] = q0; sred[wj * 6 + 4] = q1; sred[wj * 6 + 5] = q2;
        }
        __syncthreads();
        if (t < 6) {
            float tot = 0.f;
#pragma unroll
            for (int w = 0; w < 8; w++) tot += sred[w * 6 + t];
            sstat[t] = tot;
        }
        __syncthreads();
        const float mu0 = sstat[0] * (1.f / 512.f);
        const float mu1 = sstat[1] * (1.f / 512.f);
        const float mu2 = sstat[2] * (1.f / 512.f);
        const float rs0 = rsqrtf(sstat[3] * (1.f / 512.f) - mu0 * mu0 + LN_EPS);
        const float rs1 = rsqrtf(sstat[4] * (1.f / 512.f) - mu1 * mu1 + LN_EPS);
        const float rs2 = rsqrtf(sstat[5] * (1.f / 512.f) - mu2 * mu2 + LN_EPS);

        float* outt = out + ((size_t)sub * 512 + torig) * 1024 + dir * 512;
        float* hwr = g_hT + dir * 32768;

        float o0, o1;
        // half 0: column t
        {
            float phz  = (v0 - mu0) * rs0 * gg6[0] + bb6[0];
            float phrv = (v2 - mu1) * rs1 * gg6[2] + bb6[2];
            float phgv = (v4 - mu2) * rs2 * gg6[4] + bb6[4];
            float z  = sig_fast(xz0 + phz);
            float r  = sig_fast(xr0 + phrv);
            float gv = tanh_fast(xg0 + r * phgv);
            h0 = h0 + m * z * (gv - h0);
            hwr[t * 64 + sub] = h0;
            o0 = h0 * m;
        }
        // half 1: column t+256
        {
            float phz  = (v1 - mu0) * rs0 * gg6[1] + bb6[1];
            float phrv = (v3 - mu1) * rs1 * gg6[3] + bb6[3];
            float phgv = (v5 - mu2) * rs2 * gg6[5] + bb6[5];
            float z  = sig_fast(xz1 + phz);
            float r  = sig_fast(xr1 + phrv);
            float gv = tanh_fast(xg1 + r * phgv);
            h1 = h1 + m * z * (gv - h1);
            hwr[(t + 256) * 64 + sub] = h1;
            o1 = h1 * m;
        }

        // ---- bar2: arrive early; overlap out-stores + next-step prefetch ----
        __syncthreads();                    // hT stores complete block-wide
        unsigned genl = 0;
        bool released = false;
        if (t == 0) {
            genl = *(volatile unsigned*)&g_gen2[dir];
            __threadfence();                // publish hT
            if (atomicAdd(&g_cnt2[dir], 1u) == 63u) {
                g_cnt2[dir] = 0u;
                __threadfence();
                *(volatile unsigned*)&g_gen2[dir] = genl + 1u;
                released = true;
            }
        }
        // overlapped work (not ordered by the barrier):
        outt[t]       = o0;
        outt[t + 256] = o1;
        if (s + 1 < L_) {
            const int nto = dir ? (510 - s) : (s + 1);
            const float* npx = pxrow + (size_t)(s + 1) * G_;
            n_m   = __ldg(mrow + nto);
            n_xz0 = __ldg(npx + t);        n_xz1 = __ldg(npx + 256 + t);
            n_xr0 = __ldg(npx + 512 + t);  n_xr1 = __ldg(npx + 768 + t);
            n_xg0 = __ldg(npx + 1024 + t); n_xg1 = __ldg(npx + 1280 + t);
        }
        if (t == 0 && !released) {
            while (*(volatile unsigned*)&g_gen2[dir] == genl) { __nanosleep(32); }
            __threadfence();
        }
        __syncthreads();
    }
}

// ---------------------------------------------------------------------------
extern "C" void kernel_launch(void* const* d_in, const int* in_sizes, int n_in,
                              void* d_out, int out_size)
{
    const float* xs    = (const float*)d_in[0];
    const float* xmask = (const float*)d_in[1];
    const float* fWx   = (const float*)d_in[2];
    const float* fWh   = (const float*)d_in[3];
    const float* fgx   = (const float*)d_in[4];
    const float* fbx   = (const float*)d_in[5];
    const float* fgh   = (const float*)d_in[6];
    const float* fbh   = (const float*)d_in[7];
    const float* bWx   = (const float*)d_in[8];
    const float* bWh   = (const float*)d_in[9];
    const float* bgx   = (const float*)d_in[10];
    const float* bbx   = (const float*)d_in[11];
    const float* bgh   = (const float*)d_in[12];
    const float* bbh   = (const float*)d_in[13];
    float* out = (float*)d_out;

    // dynamic smem: Wh slice (512*32 floats) + 2 staging buffers (2*128*64)
    const int rnn_smem = (512 * 32 + 2 * 128 * 64) * (int)sizeof(float);  // 131072
    cudaFuncSetAttribute(rnn_kernel, cudaFuncAttributeMaxDynamicSharedMemorySize, rnn_smem);

    // 1) px = xs @ Wx (both directions; dir=1 uses time-reversed xs)
    dim3 ggrid(G_ / 128, M_ / 128, 2);
    gemm_px_kernel<<<ggrid, 256>>>(xs, fWx, bWx);

    // 2) in-place LN3 on px (warp-per-chunk)
    ln3_kernel<<<2 * M_ * 3 / 8, 256>>>(fgx, fbx, bgx, bbx);

    // 3) persistent bidirectional GRU recurrence
    rnn_kernel<<<128, 256, rnn_smem>>>(fWh, bWh, fgh, fbh, bgh, bbh, xmask, out);
}